// round 2
// baseline (speedup 1.0000x reference)
#include <cuda_runtime.h>
#include <cuda_bf16.h>

#define D 64
#define N_MAX 50048
#define E_MAX 800000

// ---------------- device scratch (static, allowed) ----------------
__device__ float g_qa[N_MAX * D];
__device__ float g_ka[N_MAX * D];
__device__ float g_qb[N_MAX * D];
__device__ float g_kb[N_MAX * D];
__device__ float g_vt[N_MAX * D];
__device__ float g_vx[N_MAX * D];
__device__ float g_ot[N_MAX * D];   // raw sum: exa * vt
__device__ float g_ox[N_MAX * D];   // raw sum: exb * vx
__device__ float g_da[N_MAX];       // denom alpha
__device__ float g_db[N_MAX];       // denom beta

// ---------------- kernel 0: zero accumulators ----------------
__global__ void zero_kernel(int n) {
    int i = blockIdx.x * blockDim.x + threadIdx.x;
    int tot = n * D;
    if (i < tot) { g_ot[i] = 0.f; g_ox[i] = 0.f; }
    if (i < n)   { g_da[i] = 0.f; g_db[i] = 0.f; }
}

// ---------------- kernel 1: six node projections ----------------
// out[n][j] = sum_k in[n][k] * W[j][k] (+ b[j])
// Block: 256 threads, 64 nodes per block, blockIdx.y selects projection.
// Each thread computes a 4x4 (node x col) register tile.
struct PArgs {
    const float* in[6];
    const float* W[6];
    const float* b[6];
};

__global__ __launch_bounds__(256) void proj_kernel(PArgs a, int n) {
    __shared__ __align__(16) float s_wT[64 * 68];   // [k][j], padded
    __shared__ __align__(16) float s_inT[64 * 68];  // [k][node], padded

    int p = blockIdx.y;
    const float* in   = a.in[p];
    const float* W    = a.W[p];
    const float* bias = a.b[p];
    float* out;
    switch (p) {
        case 0: out = g_qa; break;
        case 1: out = g_ka; break;
        case 2: out = g_qb; break;
        case 3: out = g_kb; break;
        case 4: out = g_vt; break;
        default: out = g_vx; break;
    }

    int tid  = threadIdx.x;
    int base = blockIdx.x * 64;

    // Load W transposed: coalesced global read
    for (int idx = tid; idx < 4096; idx += 256) {
        int j = idx >> 6, k = idx & 63;
        s_wT[k * 68 + j] = W[idx];
    }
    // Load input tile transposed
    for (int idx = tid; idx < 4096; idx += 256) {
        int nd = idx >> 6, k = idx & 63;
        int g = base + nd;
        s_inT[k * 68 + nd] = (g < n) ? in[g * D + k] : 0.f;
    }
    __syncthreads();

    int tx = tid & 15;   // col group   -> cols 4*tx..4*tx+3
    int ty = tid >> 4;   // node group  -> nodes 4*ty..4*ty+3

    float acc[4][4] = {};
    #pragma unroll 16
    for (int k = 0; k < 64; k++) {
        float4 w4 = *(const float4*)&s_wT[k * 68 + 4 * tx];
        float4 a4 = *(const float4*)&s_inT[k * 68 + 4 * ty];
        float wv[4] = {w4.x, w4.y, w4.z, w4.w};
        float av[4] = {a4.x, a4.y, a4.z, a4.w};
        #pragma unroll
        for (int i = 0; i < 4; i++)
            #pragma unroll
            for (int j = 0; j < 4; j++)
                acc[i][j] = fmaf(av[i], wv[j], acc[i][j]);
    }

    float bv[4] = {0.f, 0.f, 0.f, 0.f};
    if (bias) {
        float4 b4 = *(const float4*)&bias[4 * tx];
        bv[0] = b4.x; bv[1] = b4.y; bv[2] = b4.z; bv[3] = b4.w;
    }

    #pragma unroll
    for (int i = 0; i < 4; i++) {
        int g = base + 4 * ty + i;
        if (g < n) {
            float4 o;
            o.x = acc[i][0] + bv[0];
            o.y = acc[i][1] + bv[1];
            o.z = acc[i][2] + bv[2];
            o.w = acc[i][3] + bv[3];
            *(float4*)&out[g * D + 4 * tx] = o;
        }
    }
}

// ---------------- kernel 2: fused edge pass ----------------
// One warp per edge. Two dot products (qa.ka, qb.kb), exp (no max needed:
// the segment-max cancels exactly in the softmax ratio and score magnitudes
// are O(1)), then unnormalized accumulation:
//   g_da[r] += exa;  g_ot[r*64..] += exa * vt[c]
//   g_db[r] += exb;  g_ox[r*64..] += exb * vx[c]
// NOTE: edge_index is int32 on the wire (JAX canonicalizes int64 -> int32
// without x64 mode).
__global__ __launch_bounds__(256) void edge_kernel(const int* __restrict__ ei,
                                                   int e, int n) {
    int warp = (blockIdx.x * blockDim.x + threadIdx.x) >> 5;
    int lane = threadIdx.x & 31;
    if (warp >= e) return;

    int r = __ldg(&ei[warp]);
    int c = __ldg(&ei[e + warp]);
    if ((unsigned)r >= (unsigned)n || (unsigned)c >= (unsigned)n) return;

    // dot products: 2 floats per lane per operand
    float2 qa = ((const float2*)(g_qa + (size_t)r * D))[lane];
    float2 ka = ((const float2*)(g_ka + (size_t)c * D))[lane];
    float2 qb = ((const float2*)(g_qb + (size_t)r * D))[lane];
    float2 kb = ((const float2*)(g_kb + (size_t)c * D))[lane];

    float pa = qa.x * ka.x + qa.y * ka.y;
    float pb = qb.x * kb.x + qb.y * kb.y;
    #pragma unroll
    for (int off = 16; off; off >>= 1) {
        pa += __shfl_xor_sync(0xFFFFFFFFu, pa, off);
        pb += __shfl_xor_sync(0xFFFFFFFFu, pb, off);
    }

    const float scale = 0.125f;  // 1/sqrt(64)
    float exa = __expf(pa * scale);
    float exb = __expf(pb * scale);

    if (lane == 0) atomicAdd(&g_da[r], exa);
    if (lane == 1) atomicAdd(&g_db[r], exb);

    // message accumulation: lanes 0-15 -> t-message, lanes 16-31 -> x-message
    int j = lane & 15;
    const float4* src = (lane < 16) ? (const float4*)(g_vt + (size_t)c * D)
                                    : (const float4*)(g_vx + (size_t)c * D);
    float        w    = (lane < 16) ? exa : exb;
    float*       dstb = (lane < 16) ? g_ot : g_ox;
    float4 v = src[j];
    float* dst = dstb + (size_t)r * D + 4 * j;
    asm volatile("red.global.add.v4.f32 [%0], {%1,%2,%3,%4};"
                 :: "l"(dst), "f"(v.x * w), "f"(v.y * w), "f"(v.z * w), "f"(v.w * w)
                 : "memory");
}

// ---------------- kernel 3: normalize + write output ----------------
// d_out layout: [out_x (N*D) | out_t (N*D)]
__global__ void finalize_kernel(float* __restrict__ out, int n) {
    int i = blockIdx.x * blockDim.x + threadIdx.x;
    int tot = n * D;
    if (i >= tot) return;
    int node = i >> 6;
    float da = g_da[node];
    float db = g_db[node];
    out[i]       = (db > 0.f) ? g_ox[i] / db : 0.f;
    out[tot + i] = (da > 0.f) ? g_ot[i] / da : 0.f;
}

// ---------------- launch ----------------
extern "C" void kernel_launch(void* const* d_in, const int* in_sizes, int n_in,
                              void* d_out, int out_size) {
    const float* x_src = (const float*)d_in[0];
    const float* x_tgt = (const float*)d_in[1];
    const float* t_src = (const float*)d_in[2];
    const float* t_tgt = (const float*)d_in[3];
    const int*   ei    = (const int*)d_in[4];
    const float* W_x  = (const float*)d_in[5];
    const float* W_t  = (const float*)d_in[6];
    const float* Ka_W = (const float*)d_in[7];
    const float* Ka_b = (const float*)d_in[8];
    const float* Qa_W = (const float*)d_in[9];
    const float* Qa_b = (const float*)d_in[10];
    const float* Kb_W = (const float*)d_in[11];
    const float* Kb_b = (const float*)d_in[12];
    const float* Qb_W = (const float*)d_in[13];
    const float* Qb_b = (const float*)d_in[14];

    int n = in_sizes[0] / D;      // 50000
    int e = in_sizes[4] / 2;      // 800000

    PArgs pa;
    pa.in[0] = t_tgt; pa.W[0] = Qa_W; pa.b[0] = Qa_b;   // q_alpha
    pa.in[1] = t_src; pa.W[1] = Ka_W; pa.b[1] = Ka_b;   // k_alpha
    pa.in[2] = x_tgt; pa.W[2] = Qb_W; pa.b[2] = Qb_b;   // q_beta
    pa.in[3] = x_src; pa.W[3] = Kb_W; pa.b[3] = Kb_b;   // k_beta
    pa.in[4] = t_src; pa.W[4] = W_t;  pa.b[4] = nullptr; // v_t
    pa.in[5] = x_src; pa.W[5] = W_x;  pa.b[5] = nullptr; // v_x

    int tot = n * D;
    zero_kernel<<<(tot + 255) / 256, 256>>>(n);
    proj_kernel<<<dim3((n + 63) / 64, 6), 256>>>(pa, n);
    edge_kernel<<<(e + 7) / 8, 256>>>(ei, e, n);
    finalize_kernel<<<(tot + 255) / 256, 256>>>((float*)d_out, n);
}

// round 3
// speedup vs baseline: 1.1909x; 1.1909x over previous
#include <cuda_runtime.h>
#include <cuda_fp16.h>

#define D 64
#define N_MAX 50048

// ---------------- device scratch (static, allowed) ----------------
// Packed half tables: row = 128 halfs = 256B.
//   g_q[node] = [q_alpha(64) | q_beta(64)]
//   g_k[node] = [k_alpha(64) | k_beta(64)]
//   g_v[node] = [v_t(64)     | v_x(64)   ]
// Packed fp32 accumulator: g_o[node] = [sum exa*vt (64) | sum exb*vx (64)]
// g_d[node] = {denom_alpha, denom_beta}
__device__ __align__(16) __half g_q[N_MAX * 128];
__device__ __align__(16) __half g_k[N_MAX * 128];
__device__ __align__(16) __half g_v[N_MAX * 128];
__device__ __align__(16) float  g_o[N_MAX * 128];
__device__ __align__(16) float2 g_d[N_MAX];

// ---------------- kernel 0: zero accumulators (vectorized) ----------------
__global__ void zero_kernel(int n) {
    int i = blockIdx.x * blockDim.x + threadIdx.x;
    int tot4 = n * 32;                 // n*128 floats / 4
    if (i < tot4) ((float4*)g_o)[i] = make_float4(0.f, 0.f, 0.f, 0.f);
    if (i < n)    g_d[i] = make_float2(0.f, 0.f);
}

// ---------------- kernel 1: six node projections -> packed half ----------
// out[n][j] = sum_k in[n][k] * W[j][k] (+ b[j]), written as half into a
// packed table at column offset 0 or 64.
struct PArgs {
    const float* in[6];
    const float* W[6];
    const float* b[6];
};

__global__ __launch_bounds__(256) void proj_kernel(PArgs a, int n) {
    __shared__ __align__(16) float s_wT[64 * 68];   // [k][j], padded
    __shared__ __align__(16) float s_inT[64 * 68];  // [k][node], padded

    int p = blockIdx.y;
    const float* in   = a.in[p];
    const float* W    = a.W[p];
    const float* bias = a.b[p];
    __half* out;
    int coloff;
    switch (p) {
        case 0: out = g_q; coloff = 0;  break;   // q_alpha
        case 1: out = g_k; coloff = 0;  break;   // k_alpha
        case 2: out = g_q; coloff = 64; break;   // q_beta
        case 3: out = g_k; coloff = 64; break;   // k_beta
        case 4: out = g_v; coloff = 0;  break;   // v_t
        default: out = g_v; coloff = 64; break;  // v_x
    }

    int tid  = threadIdx.x;
    int base = blockIdx.x * 64;

    for (int idx = tid; idx < 4096; idx += 256) {
        int j = idx >> 6, k = idx & 63;
        s_wT[k * 68 + j] = W[idx];
    }
    for (int idx = tid; idx < 4096; idx += 256) {
        int nd = idx >> 6, k = idx & 63;
        int g = base + nd;
        s_inT[k * 68 + nd] = (g < n) ? in[g * D + k] : 0.f;
    }
    __syncthreads();

    int tx = tid & 15;   // col group   -> cols 4*tx..4*tx+3
    int ty = tid >> 4;   // node group  -> nodes 4*ty..4*ty+3

    float acc[4][4] = {};
    #pragma unroll 16
    for (int k = 0; k < 64; k++) {
        float4 w4 = *(const float4*)&s_wT[k * 68 + 4 * tx];
        float4 a4 = *(const float4*)&s_inT[k * 68 + 4 * ty];
        float wv[4] = {w4.x, w4.y, w4.z, w4.w};
        float av[4] = {a4.x, a4.y, a4.z, a4.w};
        #pragma unroll
        for (int i = 0; i < 4; i++)
            #pragma unroll
            for (int j = 0; j < 4; j++)
                acc[i][j] = fmaf(av[i], wv[j], acc[i][j]);
    }

    float bv[4] = {0.f, 0.f, 0.f, 0.f};
    if (bias) {
        float4 b4 = *(const float4*)&bias[4 * tx];
        bv[0] = b4.x; bv[1] = b4.y; bv[2] = b4.z; bv[3] = b4.w;
    }

    #pragma unroll
    for (int i = 0; i < 4; i++) {
        int g = base + 4 * ty + i;
        if (g < n) {
            __half2 h0 = __floats2half2_rn(acc[i][0] + bv[0], acc[i][1] + bv[1]);
            __half2 h1 = __floats2half2_rn(acc[i][2] + bv[2], acc[i][3] + bv[3]);
            __half2* o = (__half2*)&out[(size_t)g * 128 + coloff + 4 * tx];
            o[0] = h0;
            o[1] = h1;
        }
    }
}

// ---------------- kernel 2: fused edge pass ----------------
// One warp per edge. Lanes 0-15 = alpha path, lanes 16-31 = beta path.
// Per lane: one 8B load each from q[r], k[c], v[c] rows. Segment-max is
// dropped (it cancels exactly in the softmax ratio; scores are O(1)).
__global__ __launch_bounds__(256) void edge_kernel(const int* __restrict__ ei,
                                                   int e, int n) {
    int warp = (blockIdx.x * blockDim.x + threadIdx.x) >> 5;
    int lane = threadIdx.x & 31;
    if (warp >= e) return;

    int r = __ldg(&ei[warp]);
    int c = __ldg(&ei[e + warp]);
    if ((unsigned)r >= (unsigned)n || (unsigned)c >= (unsigned)n) return;

    uint2 qu = ((const uint2*)(g_q + (size_t)r * 128))[lane];
    uint2 ku = ((const uint2*)(g_k + (size_t)c * 128))[lane];

    float2 q0 = __half22float2(*(const __half2*)&qu.x);
    float2 q1 = __half22float2(*(const __half2*)&qu.y);
    float2 k0 = __half22float2(*(const __half2*)&ku.x);
    float2 k1 = __half22float2(*(const __half2*)&ku.y);

    float p = q0.x * k0.x + q0.y * k0.y + q1.x * k1.x + q1.y * k1.y;
    // reduce within each 16-lane half-warp
    p += __shfl_xor_sync(0xFFFFFFFFu, p, 1);
    p += __shfl_xor_sync(0xFFFFFFFFu, p, 2);
    p += __shfl_xor_sync(0xFFFFFFFFu, p, 4);
    p += __shfl_xor_sync(0xFFFFFFFFu, p, 8);

    float ex = __expf(p * 0.125f);   // lanes 0-15: exp(score_a), 16-31: exp(score_b)

    if (lane == 0)
        asm volatile("red.global.add.f32 [%0], %1;" :: "l"(&g_d[r].x), "f"(ex) : "memory");
    if (lane == 16)
        asm volatile("red.global.add.f32 [%0], %1;" :: "l"(&g_d[r].y), "f"(ex) : "memory");

    uint2 vu = ((const uint2*)(g_v + (size_t)c * 128))[lane];
    float2 v0 = __half22float2(*(const __half2*)&vu.x);
    float2 v1 = __half22float2(*(const __half2*)&vu.y);

    float* dst = g_o + (size_t)r * 128 + 4 * lane;
    asm volatile("red.global.add.v4.f32 [%0], {%1,%2,%3,%4};"
                 :: "l"(dst), "f"(v0.x * ex), "f"(v0.y * ex),
                    "f"(v1.x * ex), "f"(v1.y * ex)
                 : "memory");
}

// ---------------- kernel 3: normalize + write output (vectorized) --------
// d_out layout: [out_x (N*D) | out_t (N*D)]
// g_o row: [ot(64) | ox(64)]
__global__ void finalize_kernel(float* __restrict__ out, int n) {
    int i = blockIdx.x * blockDim.x + threadIdx.x;   // one per float4 of g_o
    int tot4 = n * 32;
    if (i >= tot4) return;
    int node = i >> 5;
    int j    = i & 31;        // j<16: ot part, j>=16: ox part
    float2 d = g_d[node];
    float4 v = ((const float4*)g_o)[i];
    int totD = n * D;
    if (j < 16) {             // t-message -> out_t
        float inv = (d.x > 0.f) ? __frcp_rn(d.x) : 0.f;
        v.x *= inv; v.y *= inv; v.z *= inv; v.w *= inv;
        *(float4*)&out[totD + node * D + 4 * j] = v;
    } else {                  // x-message -> out_x
        float inv = (d.y > 0.f) ? __frcp_rn(d.y) : 0.f;
        v.x *= inv; v.y *= inv; v.z *= inv; v.w *= inv;
        *(float4*)&out[node * D + 4 * (j - 16)] = v;
    }
}

// ---------------- launch ----------------
extern "C" void kernel_launch(void* const* d_in, const int* in_sizes, int n_in,
                              void* d_out, int out_size) {
    const float* x_src = (const float*)d_in[0];
    const float* x_tgt = (const float*)d_in[1];
    const float* t_src = (const float*)d_in[2];
    const float* t_tgt = (const float*)d_in[3];
    const int*   ei    = (const int*)d_in[4];
    const float* W_x  = (const float*)d_in[5];
    const float* W_t  = (const float*)d_in[6];
    const float* Ka_W = (const float*)d_in[7];
    const float* Ka_b = (const float*)d_in[8];
    const float* Qa_W = (const float*)d_in[9];
    const float* Qa_b = (const float*)d_in[10];
    const float* Kb_W = (const float*)d_in[11];
    const float* Kb_b = (const float*)d_in[12];
    const float* Qb_W = (const float*)d_in[13];
    const float* Qb_b = (const float*)d_in[14];

    int n = in_sizes[0] / D;      // 50000
    int e = in_sizes[4] / 2;      // 800000

    PArgs pa;
    pa.in[0] = t_tgt; pa.W[0] = Qa_W; pa.b[0] = Qa_b;    // q_alpha
    pa.in[1] = t_src; pa.W[1] = Ka_W; pa.b[1] = Ka_b;    // k_alpha
    pa.in[2] = x_tgt; pa.W[2] = Qb_W; pa.b[2] = Qb_b;    // q_beta
    pa.in[3] = x_src; pa.W[3] = Kb_W; pa.b[3] = Kb_b;    // k_beta
    pa.in[4] = t_src; pa.W[4] = W_t;  pa.b[4] = nullptr; // v_t
    pa.in[5] = x_src; pa.W[5] = W_x;  pa.b[5] = nullptr; // v_x

    int tot4 = n * 32;
    zero_kernel<<<(tot4 + 255) / 256, 256>>>(n);
    proj_kernel<<<dim3((n + 63) / 64, 6), 256>>>(pa, n);
    edge_kernel<<<(e + 7) / 8, 256>>>(ei, e, n);
    finalize_kernel<<<(tot4 + 255) / 256, 256>>>((float*)d_out, n);
}

// round 4
// speedup vs baseline: 1.3184x; 1.1070x over previous
#include <cuda_runtime.h>
#include <cuda_fp16.h>

#define D 64
#define N_MAX 50048
#define E_MAX 800000

// ---------------- device scratch (static, allowed) ----------------
// Packed half tables: row = 128 halfs = 256B.
//   g_q[node] = [q_alpha(64) | q_beta(64)]
//   g_k[node] = [k_alpha(64) | k_beta(64)]
//   g_v[node] = [v_t(64)     | v_x(64)   ]
__device__ __align__(16) __half g_q[N_MAX * 128];
__device__ __align__(16) __half g_k[N_MAX * 128];
__device__ __align__(16) __half g_v[N_MAX * 128];

// CSR-style bucketing of edges by destination (row)
__device__ int g_cnt[N_MAX];      // in-degree
__device__ int g_start[N_MAX];    // exclusive prefix sum
__device__ int g_cursor[N_MAX];   // fill cursor (== end after scatter)
__device__ int g_sc[E_MAX];       // col index per bucketed edge

// ---------------- kernel 0: zero counters ----------------
__global__ void zero_cnt_kernel(int n) {
    int i = blockIdx.x * blockDim.x + threadIdx.x;
    if (i < n) g_cnt[i] = 0;
}

// ---------------- kernel 1: six node projections -> packed half ----------
struct PArgs {
    const float* in[6];
    const float* W[6];
    const float* b[6];
};

__global__ __launch_bounds__(256) void proj_kernel(PArgs a, int n) {
    __shared__ __align__(16) float s_wT[64 * 68];   // [k][j], padded
    __shared__ __align__(16) float s_inT[64 * 68];  // [k][node], padded

    int p = blockIdx.y;
    const float* in   = a.in[p];
    const float* W    = a.W[p];
    const float* bias = a.b[p];
    __half* out;
    int coloff;
    switch (p) {
        case 0: out = g_q; coloff = 0;  break;   // q_alpha
        case 1: out = g_k; coloff = 0;  break;   // k_alpha
        case 2: out = g_q; coloff = 64; break;   // q_beta
        case 3: out = g_k; coloff = 64; break;   // k_beta
        case 4: out = g_v; coloff = 0;  break;   // v_t
        default: out = g_v; coloff = 64; break;  // v_x
    }

    int tid  = threadIdx.x;
    int base = blockIdx.x * 64;

    for (int idx = tid; idx < 4096; idx += 256) {
        int j = idx >> 6, k = idx & 63;
        s_wT[k * 68 + j] = W[idx];
    }
    for (int idx = tid; idx < 4096; idx += 256) {
        int nd = idx >> 6, k = idx & 63;
        int g = base + nd;
        s_inT[k * 68 + nd] = (g < n) ? in[g * D + k] : 0.f;
    }
    __syncthreads();

    int tx = tid & 15;   // cols 4*tx..4*tx+3
    int ty = tid >> 4;   // nodes 4*ty..4*ty+3

    float acc[4][4] = {};
    #pragma unroll 16
    for (int k = 0; k < 64; k++) {
        float4 w4 = *(const float4*)&s_wT[k * 68 + 4 * tx];
        float4 a4 = *(const float4*)&s_inT[k * 68 + 4 * ty];
        float wv[4] = {w4.x, w4.y, w4.z, w4.w};
        float av[4] = {a4.x, a4.y, a4.z, a4.w};
        #pragma unroll
        for (int i = 0; i < 4; i++)
            #pragma unroll
            for (int j = 0; j < 4; j++)
                acc[i][j] = fmaf(av[i], wv[j], acc[i][j]);
    }

    float bv[4] = {0.f, 0.f, 0.f, 0.f};
    if (bias) {
        float4 b4 = *(const float4*)&bias[4 * tx];
        bv[0] = b4.x; bv[1] = b4.y; bv[2] = b4.z; bv[3] = b4.w;
    }

    #pragma unroll
    for (int i = 0; i < 4; i++) {
        int g = base + 4 * ty + i;
        if (g < n) {
            __half2 h0 = __floats2half2_rn(acc[i][0] + bv[0], acc[i][1] + bv[1]);
            __half2 h1 = __floats2half2_rn(acc[i][2] + bv[2], acc[i][3] + bv[3]);
            __half2* o = (__half2*)&out[(size_t)g * 128 + coloff + 4 * tx];
            o[0] = h0;
            o[1] = h1;
        }
    }
}

// ---------------- kernel 2: histogram of destinations ----------------
__global__ void hist_kernel(const int* __restrict__ ei, int e, int n) {
    int i = blockIdx.x * blockDim.x + threadIdx.x;
    if (i >= e) return;
    int r = __ldg(&ei[i]);
    if ((unsigned)r < (unsigned)n) atomicAdd(&g_cnt[r], 1);
}

// ---------------- kernel 3: exclusive prefix scan (single block) --------
__global__ __launch_bounds__(1024) void scan_kernel(int n) {
    __shared__ int s_w[32];
    __shared__ int s_base;
    int tid = threadIdx.x;
    if (tid == 0) s_base = 0;
    __syncthreads();
    for (int base = 0; base < n; base += 1024) {
        int i = base + tid;
        int v = (i < n) ? g_cnt[i] : 0;
        int x = v;
        #pragma unroll
        for (int o = 1; o < 32; o <<= 1) {
            int t = __shfl_up_sync(0xFFFFFFFFu, x, o);
            if ((tid & 31) >= o) x += t;
        }
        if ((tid & 31) == 31) s_w[tid >> 5] = x;
        __syncthreads();
        if (tid < 32) {
            int w = s_w[tid];
            #pragma unroll
            for (int o = 1; o < 32; o <<= 1) {
                int t = __shfl_up_sync(0xFFFFFFFFu, w, o);
                if (tid >= o) w += t;
            }
            s_w[tid] = w;   // inclusive over warp totals
        }
        __syncthreads();
        int warp = tid >> 5;
        int woff = (warp == 0) ? 0 : s_w[warp - 1];
        int excl = s_base + woff + x - v;
        if (i < n) { g_start[i] = excl; g_cursor[i] = excl; }
        __syncthreads();
        if (tid == 0) s_base += s_w[31];
        __syncthreads();
    }
}

// ---------------- kernel 4: bucket the col indices by destination --------
__global__ void scatter_kernel(const int* __restrict__ ei, int e, int n) {
    int i = blockIdx.x * blockDim.x + threadIdx.x;
    if (i >= e) return;
    int r = __ldg(&ei[i]);
    int c = __ldg(&ei[e + i]);
    if ((unsigned)r >= (unsigned)n || (unsigned)c >= (unsigned)n) return;
    int pos = atomicAdd(&g_cursor[r], 1);
    g_sc[pos] = c;
}

// ---------------- kernel 5: per-node gather + softmax + aggregate --------
// One warp per destination node. Lanes 0-15 = alpha/t path, 16-31 = beta/x.
// Registers accumulate everything; no FP atomics; fuses normalization and
// output write. Segment-max dropped (cancels exactly in softmax ratio).
// d_out layout: [out_x (N*D) | out_t (N*D)]
__global__ __launch_bounds__(256) void node_kernel(float* __restrict__ out, int n) {
    int warp = (blockIdx.x * blockDim.x + threadIdx.x) >> 5;
    int lane = threadIdx.x & 31;
    if (warp >= n) return;
    int r = warp;

    int j    = g_start[r];
    int jend = g_cursor[r];   // == start + count after scatter

    uint2 qu = ((const uint2*)(g_q + (size_t)r * 128))[lane];
    float2 q0 = __half22float2(*(const __half2*)&qu.x);
    float2 q1 = __half22float2(*(const __half2*)&qu.y);

    float4 acc = make_float4(0.f, 0.f, 0.f, 0.f);
    float  den = 0.f;

    // depth-1 software pipeline
    uint2 ku_n = make_uint2(0, 0), vu_n = make_uint2(0, 0);
    if (j < jend) {
        int c = __ldg(&g_sc[j]);
        ku_n = ((const uint2*)(g_k + (size_t)c * 128))[lane];
        vu_n = ((const uint2*)(g_v + (size_t)c * 128))[lane];
    }

    while (j < jend) {
        uint2 ku = ku_n, vu = vu_n;
        int jn = j + 1;
        if (jn < jend) {
            int c = __ldg(&g_sc[jn]);
            ku_n = ((const uint2*)(g_k + (size_t)c * 128))[lane];
            vu_n = ((const uint2*)(g_v + (size_t)c * 128))[lane];
        }
        j = jn;

        float2 k0 = __half22float2(*(const __half2*)&ku.x);
        float2 k1 = __half22float2(*(const __half2*)&ku.y);
        float p = q0.x * k0.x + q0.y * k0.y + q1.x * k1.x + q1.y * k1.y;
        // reduce within each 16-lane half-warp
        p += __shfl_xor_sync(0xFFFFFFFFu, p, 1);
        p += __shfl_xor_sync(0xFFFFFFFFu, p, 2);
        p += __shfl_xor_sync(0xFFFFFFFFu, p, 4);
        p += __shfl_xor_sync(0xFFFFFFFFu, p, 8);

        float ex = __expf(p * 0.125f);
        den += ex;

        float2 v0 = __half22float2(*(const __half2*)&vu.x);
        float2 v1 = __half22float2(*(const __half2*)&vu.y);
        acc.x = fmaf(ex, v0.x, acc.x);
        acc.y = fmaf(ex, v0.y, acc.y);
        acc.z = fmaf(ex, v1.x, acc.z);
        acc.w = fmaf(ex, v1.y, acc.w);
    }

    float inv = (den > 0.f) ? __frcp_rn(den) : 0.f;
    acc.x *= inv; acc.y *= inv; acc.z *= inv; acc.w *= inv;

    int totD = n * D;
    if (lane < 16) {   // t-message -> out_t
        *(float4*)&out[totD + r * D + 4 * lane] = acc;
    } else {           // x-message -> out_x
        *(float4*)&out[r * D + 4 * (lane - 16)] = acc;
    }
}

// ---------------- launch ----------------
extern "C" void kernel_launch(void* const* d_in, const int* in_sizes, int n_in,
                              void* d_out, int out_size) {
    const float* x_src = (const float*)d_in[0];
    const float* x_tgt = (const float*)d_in[1];
    const float* t_src = (const float*)d_in[2];
    const float* t_tgt = (const float*)d_in[3];
    const int*   ei    = (const int*)d_in[4];
    const float* W_x  = (const float*)d_in[5];
    const float* W_t  = (const float*)d_in[6];
    const float* Ka_W = (const float*)d_in[7];
    const float* Ka_b = (const float*)d_in[8];
    const float* Qa_W = (const float*)d_in[9];
    const float* Qa_b = (const float*)d_in[10];
    const float* Kb_W = (const float*)d_in[11];
    const float* Kb_b = (const float*)d_in[12];
    const float* Qb_W = (const float*)d_in[13];
    const float* Qb_b = (const float*)d_in[14];

    int n = in_sizes[0] / D;      // 50000
    int e = in_sizes[4] / 2;      // 800000

    PArgs pa;
    pa.in[0] = t_tgt; pa.W[0] = Qa_W; pa.b[0] = Qa_b;    // q_alpha
    pa.in[1] = t_src; pa.W[1] = Ka_W; pa.b[1] = Ka_b;    // k_alpha
    pa.in[2] = x_tgt; pa.W[2] = Qb_W; pa.b[2] = Qb_b;    // q_beta
    pa.in[3] = x_src; pa.W[3] = Kb_W; pa.b[3] = Kb_b;    // k_beta
    pa.in[4] = t_src; pa.W[4] = W_t;  pa.b[4] = nullptr; // v_t
    pa.in[5] = x_src; pa.W[5] = W_x;  pa.b[5] = nullptr; // v_x

    zero_cnt_kernel<<<(n + 255) / 256, 256>>>(n);
    hist_kernel<<<(e + 255) / 256, 256>>>(ei, e, n);
    proj_kernel<<<dim3((n + 63) / 64, 6), 256>>>(pa, n);
    scan_kernel<<<1, 1024>>>(n);
    scatter_kernel<<<(e + 255) / 256, 256>>>(ei, e, n);
    node_kernel<<<(n * 32 + 255) / 256, 256>>>((float*)d_out, n);
}

// round 5
// speedup vs baseline: 1.5917x; 1.2073x over previous
#include <cuda_runtime.h>
#include <cuda_fp16.h>

#define D 64
#define N_MAX 50048
#define E_MAX 800000
#define SCAN_BLK 256

// ---------------- device scratch (static, allowed) ----------------
// Packed half tables: row = 128 halfs = 256B.
//   g_q[node] = [q_alpha(64) | q_beta(64)]
//   g_k[node] = [k_alpha(64) | k_beta(64)]
//   g_v[node] = [v_t(64)     | v_x(64)   ]
__device__ __align__(16) __half g_q[N_MAX * 128];
__device__ __align__(16) __half g_k[N_MAX * 128];
__device__ __align__(16) __half g_v[N_MAX * 128];

// CSR-style bucketing of edges by destination (row)
__device__ int g_cnt[N_MAX];      // in-degree
__device__ int g_start[N_MAX];    // exclusive prefix sum
__device__ int g_cursor[N_MAX];   // fill cursor (== end after scatter)
__device__ int g_sc[E_MAX];       // col index per bucketed edge
__device__ int g_bsum[(N_MAX + SCAN_BLK - 1) / SCAN_BLK + 1];  // block totals

// ---------------- kernel 0: zero counters ----------------
__global__ void zero_cnt_kernel(int n) {
    int i = blockIdx.x * blockDim.x + threadIdx.x;
    if (i < n) g_cnt[i] = 0;
}

// ---------------- kernel 1: six node projections -> packed half ----------
struct PArgs {
    const float* in[6];
    const float* W[6];
    const float* b[6];
};

__global__ __launch_bounds__(256) void proj_kernel(PArgs a, int n) {
    __shared__ __align__(16) float s_wT[64 * 68];   // [k][j], padded
    __shared__ __align__(16) float s_inT[64 * 68];  // [k][node], padded

    int p = blockIdx.y;
    const float* in   = a.in[p];
    const float* W    = a.W[p];
    const float* bias = a.b[p];
    __half* out;
    int coloff;
    switch (p) {
        case 0: out = g_q; coloff = 0;  break;   // q_alpha
        case 1: out = g_k; coloff = 0;  break;   // k_alpha
        case 2: out = g_q; coloff = 64; break;   // q_beta
        case 3: out = g_k; coloff = 64; break;   // k_beta
        case 4: out = g_v; coloff = 0;  break;   // v_t
        default: out = g_v; coloff = 64; break;  // v_x
    }

    int tid  = threadIdx.x;
    int base = blockIdx.x * 64;

    for (int idx = tid; idx < 4096; idx += 256) {
        int j = idx >> 6, k = idx & 63;
        s_wT[k * 68 + j] = W[idx];
    }
    for (int idx = tid; idx < 4096; idx += 256) {
        int nd = idx >> 6, k = idx & 63;
        int g = base + nd;
        s_inT[k * 68 + nd] = (g < n) ? in[g * D + k] : 0.f;
    }
    __syncthreads();

    int tx = tid & 15;   // cols 4*tx..4*tx+3
    int ty = tid >> 4;   // nodes 4*ty..4*ty+3

    float acc[4][4] = {};
    #pragma unroll 16
    for (int k = 0; k < 64; k++) {
        float4 w4 = *(const float4*)&s_wT[k * 68 + 4 * tx];
        float4 a4 = *(const float4*)&s_inT[k * 68 + 4 * ty];
        float wv[4] = {w4.x, w4.y, w4.z, w4.w};
        float av[4] = {a4.x, a4.y, a4.z, a4.w};
        #pragma unroll
        for (int i = 0; i < 4; i++)
            #pragma unroll
            for (int j = 0; j < 4; j++)
                acc[i][j] = fmaf(av[i], wv[j], acc[i][j]);
    }

    float bv[4] = {0.f, 0.f, 0.f, 0.f};
    if (bias) {
        float4 b4 = *(const float4*)&bias[4 * tx];
        bv[0] = b4.x; bv[1] = b4.y; bv[2] = b4.z; bv[3] = b4.w;
    }

    #pragma unroll
    for (int i = 0; i < 4; i++) {
        int g = base + 4 * ty + i;
        if (g < n) {
            __half2 h0 = __floats2half2_rn(acc[i][0] + bv[0], acc[i][1] + bv[1]);
            __half2 h1 = __floats2half2_rn(acc[i][2] + bv[2], acc[i][3] + bv[3]);
            __half2* o = (__half2*)&out[(size_t)g * 128 + coloff + 4 * tx];
            o[0] = h0;
            o[1] = h1;
        }
    }
}

// ---------------- kernel 2: histogram of destinations ----------------
__global__ void hist_kernel(const int* __restrict__ ei, int e, int n) {
    int i = blockIdx.x * blockDim.x + threadIdx.x;
    if (i >= e) return;
    int r = __ldg(&ei[i]);
    if ((unsigned)r < (unsigned)n) atomicAdd(&g_cnt[r], 1);
}

// ---------------- two-level scan ----------------
// helper: 256-thread block exclusive scan; returns exclusive value, total in s_tot
__device__ __forceinline__ int block_scan_excl(int v, int tid, int* s_w, int* s_tot) {
    int x = v;
    #pragma unroll
    for (int o = 1; o < 32; o <<= 1) {
        int t = __shfl_up_sync(0xFFFFFFFFu, x, o);
        if ((tid & 31) >= o) x += t;
    }
    if ((tid & 31) == 31) s_w[tid >> 5] = x;
    __syncthreads();
    if (tid < 8) {
        int w = s_w[tid];
        #pragma unroll
        for (int o = 1; o < 8; o <<= 1) {
            int t = __shfl_up_sync(0xFFu, w, o);
            if (tid >= o) w += t;
        }
        s_w[tid] = w;
        if (tid == 7) *s_tot = w;
    }
    __syncthreads();
    int warp = tid >> 5;
    int woff = (warp == 0) ? 0 : s_w[warp - 1];
    return woff + x - v;
}

// S1: per-block local scan, emit block totals
__global__ __launch_bounds__(SCAN_BLK) void scan1_kernel(int n) {
    __shared__ int s_w[8];
    __shared__ int s_tot;
    int tid = threadIdx.x;
    int i = blockIdx.x * SCAN_BLK + tid;
    int v = (i < n) ? g_cnt[i] : 0;
    int excl = block_scan_excl(v, tid, s_w, &s_tot);
    if (i < n) g_start[i] = excl;            // local exclusive scan
    if (tid == 0) g_bsum[blockIdx.x] = s_tot;
}

// S2: scan block totals (nb <= 256)
__global__ __launch_bounds__(SCAN_BLK) void scan2_kernel(int nb) {
    __shared__ int s_w[8];
    __shared__ int s_tot;
    int tid = threadIdx.x;
    int v = (tid < nb) ? g_bsum[tid] : 0;
    int excl = block_scan_excl(v, tid, s_w, &s_tot);
    if (tid < nb) g_bsum[tid] = excl;
}

// S3: add block offsets
__global__ __launch_bounds__(SCAN_BLK) void scan3_kernel(int n) {
    int i = blockIdx.x * SCAN_BLK + threadIdx.x;
    if (i >= n) return;
    int g = g_start[i] + g_bsum[blockIdx.x];
    g_start[i]  = g;
    g_cursor[i] = g;
}

// ---------------- kernel 4: bucket the col indices by destination --------
__global__ void scatter_kernel(const int* __restrict__ ei, int e, int n) {
    int i = blockIdx.x * blockDim.x + threadIdx.x;
    if (i >= e) return;
    int r = __ldg(&ei[i]);
    int c = __ldg(&ei[e + i]);
    if ((unsigned)r >= (unsigned)n || (unsigned)c >= (unsigned)n) return;
    int pos = atomicAdd(&g_cursor[r], 1);
    g_sc[pos] = c;
}

// ---------------- kernel 5: per-node gather + softmax + aggregate --------
// One warp per destination node. Lanes 0-15 = alpha/t path, 16-31 = beta/x.
// Registers accumulate everything; no FP atomics; fuses normalization and
// output write. Segment-max dropped (cancels exactly in softmax ratio).
// d_out layout: [out_x (N*D) | out_t (N*D)]
__global__ __launch_bounds__(256) void node_kernel(float* __restrict__ out, int n) {
    int warp = (blockIdx.x * blockDim.x + threadIdx.x) >> 5;
    int lane = threadIdx.x & 31;
    if (warp >= n) return;
    int r = warp;

    int j    = g_start[r];
    int jend = g_cursor[r];   // == start + count after scatter

    uint2 qu = ((const uint2*)(g_q + (size_t)r * 128))[lane];
    float2 q0 = __half22float2(*(const __half2*)&qu.x);
    float2 q1 = __half22float2(*(const __half2*)&qu.y);

    float4 acc = make_float4(0.f, 0.f, 0.f, 0.f);
    float  den = 0.f;

    // depth-1 software pipeline
    uint2 ku_n = make_uint2(0, 0), vu_n = make_uint2(0, 0);
    if (j < jend) {
        int c = __ldg(&g_sc[j]);
        ku_n = ((const uint2*)(g_k + (size_t)c * 128))[lane];
        vu_n = ((const uint2*)(g_v + (size_t)c * 128))[lane];
    }

    while (j < jend) {
        uint2 ku = ku_n, vu = vu_n;
        int jn = j + 1;
        if (jn < jend) {
            int c = __ldg(&g_sc[jn]);
            ku_n = ((const uint2*)(g_k + (size_t)c * 128))[lane];
            vu_n = ((const uint2*)(g_v + (size_t)c * 128))[lane];
        }
        j = jn;

        float2 k0 = __half22float2(*(const __half2*)&ku.x);
        float2 k1 = __half22float2(*(const __half2*)&ku.y);
        float p = q0.x * k0.x + q0.y * k0.y + q1.x * k1.x + q1.y * k1.y;
        // reduce within each 16-lane half-warp
        p += __shfl_xor_sync(0xFFFFFFFFu, p, 1);
        p += __shfl_xor_sync(0xFFFFFFFFu, p, 2);
        p += __shfl_xor_sync(0xFFFFFFFFu, p, 4);
        p += __shfl_xor_sync(0xFFFFFFFFu, p, 8);

        float ex = __expf(p * 0.125f);
        den += ex;

        float2 v0 = __half22float2(*(const __half2*)&vu.x);
        float2 v1 = __half22float2(*(const __half2*)&vu.y);
        acc.x = fmaf(ex, v0.x, acc.x);
        acc.y = fmaf(ex, v0.y, acc.y);
        acc.z = fmaf(ex, v1.x, acc.z);
        acc.w = fmaf(ex, v1.y, acc.w);
    }

    float inv = (den > 0.f) ? __frcp_rn(den) : 0.f;
    acc.x *= inv; acc.y *= inv; acc.z *= inv; acc.w *= inv;

    int totD = n * D;
    if (lane < 16) {   // t-message -> out_t
        *(float4*)&out[totD + r * D + 4 * lane] = acc;
    } else {           // x-message -> out_x
        *(float4*)&out[r * D + 4 * (lane - 16)] = acc;
    }
}

// ---------------- launch ----------------
extern "C" void kernel_launch(void* const* d_in, const int* in_sizes, int n_in,
                              void* d_out, int out_size) {
    const float* x_src = (const float*)d_in[0];
    const float* x_tgt = (const float*)d_in[1];
    const float* t_src = (const float*)d_in[2];
    const float* t_tgt = (const float*)d_in[3];
    const int*   ei    = (const int*)d_in[4];
    const float* W_x  = (const float*)d_in[5];
    const float* W_t  = (const float*)d_in[6];
    const float* Ka_W = (const float*)d_in[7];
    const float* Ka_b = (const float*)d_in[8];
    const float* Qa_W = (const float*)d_in[9];
    const float* Qa_b = (const float*)d_in[10];
    const float* Kb_W = (const float*)d_in[11];
    const float* Kb_b = (const float*)d_in[12];
    const float* Qb_W = (const float*)d_in[13];
    const float* Qb_b = (const float*)d_in[14];

    int n = in_sizes[0] / D;      // 50000
    int e = in_sizes[4] / 2;      // 800000

    PArgs pa;
    pa.in[0] = t_tgt; pa.W[0] = Qa_W; pa.b[0] = Qa_b;    // q_alpha
    pa.in[1] = t_src; pa.W[1] = Ka_W; pa.b[1] = Ka_b;    // k_alpha
    pa.in[2] = x_tgt; pa.W[2] = Qb_W; pa.b[2] = Qb_b;    // q_beta
    pa.in[3] = x_src; pa.W[3] = Kb_W; pa.b[3] = Kb_b;    // k_beta
    pa.in[4] = t_src; pa.W[4] = W_t;  pa.b[4] = nullptr; // v_t
    pa.in[5] = x_src; pa.W[5] = W_x;  pa.b[5] = nullptr; // v_x

    int nb = (n + SCAN_BLK - 1) / SCAN_BLK;   // 196 blocks

    zero_cnt_kernel<<<(n + 255) / 256, 256>>>(n);
    hist_kernel<<<(e + 255) / 256, 256>>>(ei, e, n);
    proj_kernel<<<dim3((n + 63) / 64, 6), 256>>>(pa, n);
    scan1_kernel<<<nb, SCAN_BLK>>>(n);
    scan2_kernel<<<1, SCAN_BLK>>>(nb);
    scan3_kernel<<<nb, SCAN_BLK>>>(n);
    scatter_kernel<<<(e + 255) / 256, 256>>>(ei, e, n);
    node_kernel<<<(n * 32 + 255) / 256, 256>>>((float*)d_out, n);
}

// round 6
// speedup vs baseline: 2.8255x; 1.7751x over previous
#include <cuda_runtime.h>
#include <cuda_fp16.h>
#include <mma.h>
using namespace nvcuda;

#define D 64
#define N_MAX 50048
#define E_MAX 800000
#define SCAN_BLK 256

// ---------------- device scratch (static, allowed) ----------------
// Packed half tables: row = 128 halfs = 256B.
//   g_q[node] = [q_alpha(64) | q_beta(64)]
//   g_k[node] = [k_alpha(64) | k_beta(64)]
//   g_v[node] = [v_t(64)     | v_x(64)   ]
__device__ __align__(16) __half g_q[N_MAX * 128];
__device__ __align__(16) __half g_k[N_MAX * 128];
__device__ __align__(16) __half g_v[N_MAX * 128];

// CSR-style bucketing of edges by destination (row)
__device__ int g_cnt[N_MAX];      // in-degree (zero-init at load; scan1 re-zeros)
__device__ int g_start[N_MAX];    // exclusive prefix sum
__device__ int g_cursor[N_MAX];   // fill cursor (== end after scatter)
__device__ int g_sc[E_MAX];       // col index per bucketed edge
__device__ int g_bsum[(N_MAX + SCAN_BLK - 1) / SCAN_BLK + 1];

// ---------------- kernel 1: projections via HMMA (wmma) ----------------
// out[g][j] = sum_k in[g][k] * W[j][k] (+ b[j]); inputs fp32 -> half,
// fp32 accumulate on tensor cores, half packed output.
struct PArgs {
    const float* in[6];
    const float* W[6];
    const float* b[6];
};

#define LDA 72   // half lds, multiple of 8
#define LDW 72
#define LDC 68   // float lds, multiple of 4

__global__ __launch_bounds__(256) void proj_kernel(PArgs a, int n) {
    // phase 1: sA (128x72 half = 18432B) + sW (64x72 half = 9216B)
    // phase 2: sC (128x68 float = 34816B) overlays
    __shared__ __align__(16) char sbuf[34816];
    __half* sA = (__half*)sbuf;
    __half* sW = (__half*)(sbuf + 18432);
    float*  sC = (float*)sbuf;

    int p = blockIdx.y;
    const float* in   = a.in[p];
    const float* W    = a.W[p];
    const float* bias = a.b[p];
    __half* outp;
    int coloff;
    switch (p) {
        case 0: outp = g_q; coloff = 0;  break;   // q_alpha
        case 1: outp = g_k; coloff = 0;  break;   // k_alpha
        case 2: outp = g_q; coloff = 64; break;   // q_beta
        case 3: outp = g_k; coloff = 64; break;   // k_beta
        case 4: outp = g_v; coloff = 0;  break;   // v_t
        default: outp = g_v; coloff = 64; break;  // v_x
    }

    int tid  = threadIdx.x;
    int base = blockIdx.x * 128;

    // load 128x64 fp32 input -> half smem (row-major, ld=72)
    #pragma unroll
    for (int t = 0; t < 8; t++) {
        int idx = tid + t * 256;          // over 2048 float4
        int row = idx >> 4, c4 = idx & 15;
        int g = base + row;
        float4 f = (g < n) ? ((const float4*)in)[(size_t)g * 16 + c4]
                           : make_float4(0.f, 0.f, 0.f, 0.f);
        __half2 h0 = __floats2half2_rn(f.x, f.y);
        __half2 h1 = __floats2half2_rn(f.z, f.w);
        __half2* d = (__half2*)&sA[row * LDA + c4 * 4];
        d[0] = h0; d[1] = h1;
    }
    // load W (64x64 row-major) -> half smem; W[j][k] at sW[j*LDW+k].
    // As col_major matrix_b with ld=LDW this is exactly B(k,j)=W[j][k]=W^T.
    #pragma unroll
    for (int t = 0; t < 4; t++) {
        int idx = tid + t * 256;          // over 1024 float4
        int row = idx >> 4, c4 = idx & 15;
        float4 f = ((const float4*)W)[idx];
        __half2 h0 = __floats2half2_rn(f.x, f.y);
        __half2 h1 = __floats2half2_rn(f.z, f.w);
        __half2* d = (__half2*)&sW[row * LDW + c4 * 4];
        d[0] = h0; d[1] = h1;
    }
    __syncthreads();

    // 8 warps: wm in 0..3 (32-row strip), wn in 0..1 (32-col strip)
    int w  = tid >> 5;
    int wm = w & 3, wn = w >> 2;

    wmma::fragment<wmma::accumulator, 16, 16, 16, float> c[2][2];
    #pragma unroll
    for (int i = 0; i < 2; i++)
        #pragma unroll
        for (int jj = 0; jj < 2; jj++)
            wmma::fill_fragment(c[i][jj], 0.f);

    #pragma unroll
    for (int k0 = 0; k0 < 64; k0 += 16) {
        wmma::fragment<wmma::matrix_a, 16, 16, 16, __half, wmma::row_major> af[2];
        wmma::fragment<wmma::matrix_b, 16, 16, 16, __half, wmma::col_major> bf[2];
        #pragma unroll
        for (int i = 0; i < 2; i++)
            wmma::load_matrix_sync(af[i], &sA[(wm * 32 + i * 16) * LDA + k0], LDA);
        #pragma unroll
        for (int jj = 0; jj < 2; jj++)
            wmma::load_matrix_sync(bf[jj], &sW[(wn * 32 + jj * 16) * LDW + k0], LDW);
        #pragma unroll
        for (int i = 0; i < 2; i++)
            #pragma unroll
            for (int jj = 0; jj < 2; jj++)
                wmma::mma_sync(c[i][jj], af[i], bf[jj], c[i][jj]);
    }
    __syncthreads();   // done reading sA/sW; safe to overlay sC

    #pragma unroll
    for (int i = 0; i < 2; i++)
        #pragma unroll
        for (int jj = 0; jj < 2; jj++)
            wmma::store_matrix_sync(&sC[(wm * 32 + i * 16) * LDC + wn * 32 + jj * 16],
                                    c[i][jj], LDC, wmma::mem_row_major);
    __syncthreads();

    // bias + convert + packed write (half2 per thread-iter)
    #pragma unroll
    for (int t = 0; t < 16; t++) {
        int i = tid + t * 256;            // over 128*32 col-pairs
        int row = i >> 5, pr = i & 31;
        int g = base + row;
        if (g < n) {
            float f0 = sC[row * LDC + 2 * pr];
            float f1 = sC[row * LDC + 2 * pr + 1];
            if (bias) { f0 += bias[2 * pr]; f1 += bias[2 * pr + 1]; }
            *(__half2*)&outp[(size_t)g * 128 + coloff + 2 * pr] =
                __floats2half2_rn(f0, f1);
        }
    }
}

// ---------------- kernel 2: histogram of destinations ----------------
__global__ void hist_kernel(const int* __restrict__ ei, int e, int n) {
    int i = blockIdx.x * blockDim.x + threadIdx.x;
    if (i >= e) return;
    int r = __ldg(&ei[i]);
    if ((unsigned)r < (unsigned)n) atomicAdd(&g_cnt[r], 1);
}

// ---------------- two-level scan ----------------
__device__ __forceinline__ int block_scan_excl(int v, int tid, int* s_w, int* s_tot) {
    int x = v;
    #pragma unroll
    for (int o = 1; o < 32; o <<= 1) {
        int t = __shfl_up_sync(0xFFFFFFFFu, x, o);
        if ((tid & 31) >= o) x += t;
    }
    if ((tid & 31) == 31) s_w[tid >> 5] = x;
    __syncthreads();
    if (tid < 8) {
        int w = s_w[tid];
        #pragma unroll
        for (int o = 1; o < 8; o <<= 1) {
            int t = __shfl_up_sync(0xFFu, w, o);
            if (tid >= o) w += t;
        }
        s_w[tid] = w;
        if (tid == 7) *s_tot = w;
    }
    __syncthreads();
    int warp = tid >> 5;
    int woff = (warp == 0) ? 0 : s_w[warp - 1];
    return woff + x - v;
}

// S1: per-block local scan, emit block totals; also re-zero g_cnt for the
// next launch (device globals start zeroed, so every call sees zeros).
__global__ __launch_bounds__(SCAN_BLK) void scan1_kernel(int n) {
    __shared__ int s_w[8];
    __shared__ int s_tot;
    int tid = threadIdx.x;
    int i = blockIdx.x * SCAN_BLK + tid;
    int v = (i < n) ? g_cnt[i] : 0;
    if (i < n) g_cnt[i] = 0;
    int excl = block_scan_excl(v, tid, s_w, &s_tot);
    if (i < n) g_start[i] = excl;
    if (tid == 0) g_bsum[blockIdx.x] = s_tot;
}

__global__ __launch_bounds__(SCAN_BLK) void scan2_kernel(int nb) {
    __shared__ int s_w[8];
    __shared__ int s_tot;
    int tid = threadIdx.x;
    int v = (tid < nb) ? g_bsum[tid] : 0;
    int excl = block_scan_excl(v, tid, s_w, &s_tot);
    if (tid < nb) g_bsum[tid] = excl;
}

__global__ __launch_bounds__(SCAN_BLK) void scan3_kernel(int n) {
    int i = blockIdx.x * SCAN_BLK + threadIdx.x;
    if (i >= n) return;
    int g = g_start[i] + g_bsum[blockIdx.x];
    g_start[i]  = g;
    g_cursor[i] = g;
}

// ---------------- kernel 4: bucket the col indices by destination --------
__global__ void scatter_kernel(const int* __restrict__ ei, int e, int n) {
    int i = blockIdx.x * blockDim.x + threadIdx.x;
    if (i >= e) return;
    int r = __ldg(&ei[i]);
    int c = __ldg(&ei[e + i]);
    if ((unsigned)r >= (unsigned)n || (unsigned)c >= (unsigned)n) return;
    int pos = atomicAdd(&g_cursor[r], 1);
    g_sc[pos] = c;
}

// ---------------- kernel 5: per-node gather + softmax + aggregate --------
// One warp per destination node, 2 edges in flight (independent shfl chains
// for ILP), depth-1 pair prefetch. Lanes 0-15 alpha/t, 16-31 beta/x.
__global__ __launch_bounds__(256) void node_kernel(float* __restrict__ out, int n) {
    int warp = (blockIdx.x * blockDim.x + threadIdx.x) >> 5;
    int lane = threadIdx.x & 31;
    if (warp >= n) return;
    int r = warp;

    int j    = g_start[r];
    int jend = g_cursor[r];

    uint2 qu = ((const uint2*)(g_q + (size_t)r * 128))[lane];
    float2 q0 = __half22float2(*(const __half2*)&qu.x);
    float2 q1 = __half22float2(*(const __half2*)&qu.y);

    float4 acc = make_float4(0.f, 0.f, 0.f, 0.f);
    float  den = 0.f;

    uint2 kA = make_uint2(0,0), vA = make_uint2(0,0);
    uint2 kB = make_uint2(0,0), vB = make_uint2(0,0);
    if (j < jend) {
        int c = __ldg(&g_sc[j]);
        kA = ((const uint2*)(g_k + (size_t)c * 128))[lane];
        vA = ((const uint2*)(g_v + (size_t)c * 128))[lane];
    }
    if (j + 1 < jend) {
        int c = __ldg(&g_sc[j + 1]);
        kB = ((const uint2*)(g_k + (size_t)c * 128))[lane];
        vB = ((const uint2*)(g_v + (size_t)c * 128))[lane];
    }

    while (j < jend) {
        uint2 k0 = kA, v0 = vA, k1 = kB, v1 = vB;
        int rem = jend - j;
        int jn = j + 2;
        if (jn < jend) {
            int c = __ldg(&g_sc[jn]);
            kA = ((const uint2*)(g_k + (size_t)c * 128))[lane];
            vA = ((const uint2*)(g_v + (size_t)c * 128))[lane];
        }
        if (jn + 1 < jend) {
            int c = __ldg(&g_sc[jn + 1]);
            kB = ((const uint2*)(g_k + (size_t)c * 128))[lane];
            vB = ((const uint2*)(g_v + (size_t)c * 128))[lane];
        }
        j = jn;

        float2 ka0 = __half22float2(*(const __half2*)&k0.x);
        float2 ka1 = __half22float2(*(const __half2*)&k0.y);
        float2 kb0 = __half22float2(*(const __half2*)&k1.x);
        float2 kb1 = __half22float2(*(const __half2*)&k1.y);

        float p0 = q0.x * ka0.x + q0.y * ka0.y + q1.x * ka1.x + q1.y * ka1.y;
        float p1 = q0.x * kb0.x + q0.y * kb0.y + q1.x * kb1.x + q1.y * kb1.y;

        // two independent 16-lane reductions, interleaved for ILP
        p0 += __shfl_xor_sync(0xFFFFFFFFu, p0, 1);
        p1 += __shfl_xor_sync(0xFFFFFFFFu, p1, 1);
        p0 += __shfl_xor_sync(0xFFFFFFFFu, p0, 2);
        p1 += __shfl_xor_sync(0xFFFFFFFFu, p1, 2);
        p0 += __shfl_xor_sync(0xFFFFFFFFu, p0, 4);
        p1 += __shfl_xor_sync(0xFFFFFFFFu, p1, 4);
        p0 += __shfl_xor_sync(0xFFFFFFFFu, p0, 8);
        p1 += __shfl_xor_sync(0xFFFFFFFFu, p1, 8);

        float ex0 = __expf(p0 * 0.125f);
        float ex1 = (rem > 1) ? __expf(p1 * 0.125f) : 0.f;  // k1/v1 are zeros when invalid
        den += ex0 + ex1;

        float2 va0 = __half22float2(*(const __half2*)&v0.x);
        float2 va1 = __half22float2(*(const __half2*)&v0.y);
        float2 vb0 = __half22float2(*(const __half2*)&v1.x);
        float2 vb1 = __half22float2(*(const __half2*)&v1.y);

        acc.x = fmaf(ex0, va0.x, fmaf(ex1, vb0.x, acc.x));
        acc.y = fmaf(ex0, va0.y, fmaf(ex1, vb0.y, acc.y));
        acc.z = fmaf(ex0, va1.x, fmaf(ex1, vb1.x, acc.z));
        acc.w = fmaf(ex0, va1.y, fmaf(ex1, vb1.y, acc.w));
    }

    float inv = (den > 0.f) ? __frcp_rn(den) : 0.f;
    acc.x *= inv; acc.y *= inv; acc.z *= inv; acc.w *= inv;

    int totD = n * D;
    if (lane < 16) {   // t-message -> out_t
        *(float4*)&out[totD + r * D + 4 * lane] = acc;
    } else {           // x-message -> out_x
        *(float4*)&out[r * D + 4 * (lane - 16)] = acc;
    }
}

// ---------------- launch ----------------
extern "C" void kernel_launch(void* const* d_in, const int* in_sizes, int n_in,
                              void* d_out, int out_size) {
    const float* x_src = (const float*)d_in[0];
    const float* x_tgt = (const float*)d_in[1];
    const float* t_src = (const float*)d_in[2];
    const float* t_tgt = (const float*)d_in[3];
    const int*   ei    = (const int*)d_in[4];
    const float* W_x  = (const float*)d_in[5];
    const float* W_t  = (const float*)d_in[6];
    const float* Ka_W = (const float*)d_in[7];
    const float* Ka_b = (const float*)d_in[8];
    const float* Qa_W = (const float*)d_in[9];
    const float* Qa_b = (const float*)d_in[10];
    const float* Kb_W = (const float*)d_in[11];
    const float* Kb_b = (const float*)d_in[12];
    const float* Qb_W = (const float*)d_in[13];
    const float* Qb_b = (const float*)d_in[14];

    int n = in_sizes[0] / D;      // 50000
    int e = in_sizes[4] / 2;      // 800000

    PArgs pa;
    pa.in[0] = t_tgt; pa.W[0] = Qa_W; pa.b[0] = Qa_b;    // q_alpha
    pa.in[1] = t_src; pa.W[1] = Ka_W; pa.b[1] = Ka_b;    // k_alpha
    pa.in[2] = x_tgt; pa.W[2] = Qb_W; pa.b[2] = Qb_b;    // q_beta
    pa.in[3] = x_src; pa.W[3] = Kb_W; pa.b[3] = Kb_b;    // k_beta
    pa.in[4] = t_src; pa.W[4] = W_t;  pa.b[4] = nullptr; // v_t
    pa.in[5] = x_src; pa.W[5] = W_x;  pa.b[5] = nullptr; // v_x

    int nb = (n + SCAN_BLK - 1) / SCAN_BLK;

    hist_kernel<<<(e + 255) / 256, 256>>>(ei, e, n);
    proj_kernel<<<dim3((n + 127) / 128, 6), 256>>>(pa, n);
    scan1_kernel<<<nb, SCAN_BLK>>>(n);
    scan2_kernel<<<1, SCAN_BLK>>>(nb);
    scan3_kernel<<<nb, SCAN_BLK>>>(n);
    scatter_kernel<<<(e + 255) / 256, 256>>>(ei, e, n);
    node_kernel<<<(n * 32 + 255) / 256, 256>>>((float*)d_out, n);
}